// round 1
// baseline (speedup 1.0000x reference)
#include <cuda_runtime.h>
#include <math.h>

// Problem constants
#define Tn 4096   // tokens (B*S)
#define Hn 1024   // hidden
#define En 8      // experts
#define In 1024   // intermediate

// GEMM tiling
#define BM 128
#define BN 64
#define BK 16

// -------- scratch (static device globals; no allocation) --------
__device__ int   g_cnt[En];                      // tokens routed per expert
__device__ float g_imp[En];                      // sum of router probs per expert
__device__ int   g_tok[En * Tn];                 // token index lists per expert
__device__ float g_wt [En * Tn];                 // normalized combine weight per (expert,pos)
__device__ float g_inter[(size_t)En * Tn * In];  // silu(g)*u intermediate, 128 MB

// -------- init: zero output + counters --------
__global__ void init_kernel(float* out, int n) {
    int i = blockIdx.x * blockDim.x + threadIdx.x;
    if (i < n) out[i] = 0.0f;
    if (blockIdx.x == 0 && threadIdx.x < En) {
        g_cnt[threadIdx.x] = 0;
        g_imp[threadIdx.x] = 0.0f;
    }
}

// -------- router: logits, softmax, top-2, list build --------
__global__ void router_kernel(const float* __restrict__ x,
                              const float* __restrict__ Wr) {
    int t = blockIdx.x;
    int warp = threadIdx.x >> 5;
    int lane = threadIdx.x & 31;
    const float* xt = x + (size_t)t * Hn;

    // warp w computes logit for expert w
    float acc = 0.0f;
    for (int h = lane; h < Hn; h += 32)
        acc += xt[h] * Wr[h * En + warp];
    #pragma unroll
    for (int o = 16; o > 0; o >>= 1)
        acc += __shfl_xor_sync(0xffffffff, acc, o);

    __shared__ float logits[En];
    if (lane == 0) logits[warp] = acc;
    __syncthreads();

    if (threadIdx.x == 0) {
        float mx = logits[0];
        #pragma unroll
        for (int e = 1; e < En; e++) mx = fmaxf(mx, logits[e]);
        float p[En], s = 0.0f;
        #pragma unroll
        for (int e = 0; e < En; e++) { p[e] = expf(logits[e] - mx); s += p[e]; }
        float inv = 1.0f / s;
        #pragma unroll
        for (int e = 0; e < En; e++) {
            p[e] *= inv;
            atomicAdd(&g_imp[e], p[e]);
        }
        // top-2 with earliest-index tie-break (matches lax.top_k)
        int i0 = 0;
        #pragma unroll
        for (int e = 1; e < En; e++) if (p[e] > p[i0]) i0 = e;
        int i1 = (i0 == 0) ? 1 : 0;
        #pragma unroll
        for (int e = 0; e < En; e++) if (e != i0 && p[e] > p[i1]) i1 = e;
        float w0 = p[i0], w1 = p[i1];
        float sw = fmaxf(w0 + w1, 1e-9f);
        w0 /= sw; w1 /= sw;
        int p0 = atomicAdd(&g_cnt[i0], 1);
        g_tok[i0 * Tn + p0] = t;  g_wt[i0 * Tn + p0] = w0;
        int p1 = atomicAdd(&g_cnt[i1], 1);
        g_tok[i1 * Tn + p1] = t;  g_wt[i1 * Tn + p1] = w1;
    }
}

// -------- aux loss --------
__global__ void aux_kernel(float* out, int aux_idx) {
    if (threadIdx.x == 0) {
        float s = 0.0f;
        #pragma unroll
        for (int e = 0; e < En; e++)
            s += ((float)g_cnt[e] / (float)Tn) * (g_imp[e] / (float)Tn);
        out[aux_idx] = (float)En * s * 0.01f;
    }
}

// -------- GEMM1: gathered X @ {Wg, Wu}, fused silu-mul --------
__global__ __launch_bounds__(256, 2)
void gemm1_kernel(const float* __restrict__ x,
                  const float* __restrict__ Wg,
                  const float* __restrict__ Wu) {
    int e = blockIdx.z;
    int n_rows = g_cnt[e];
    int mBase = blockIdx.y * BM;
    if (mBase >= n_rows) return;
    int n0 = blockIdx.x * BN;

    __shared__ float sA[BM][BK + 4];   // row stride 20 floats (16B-aligned float4 stores)
    __shared__ float sG[BK][BN];
    __shared__ float sU[BK][BN];
    __shared__ int   sTok[BM];

    int tid = threadIdx.x;
    int tx = tid & 15;       // n direction (4 cols each)
    int ty = tid >> 4;       // m direction (8 rows each)

    if (tid < BM) {
        int m = mBase + tid;
        sTok[tid] = (m < n_rows) ? g_tok[e * Tn + m] : -1;
    }
    __syncthreads();

    float accG[8][4] = {{0}}, accU[8][4] = {{0}};
    const float* Wg_e = Wg + (size_t)e * Hn * In;
    const float* Wu_e = Wu + (size_t)e * Hn * In;

    for (int k0 = 0; k0 < Hn; k0 += BK) {
        // load A tile (gathered token rows)
        #pragma unroll
        for (int j = 0; j < 2; j++) {
            int idx = tid + j * 256;      // 0..511
            int row = idx >> 2;
            int c4  = (idx & 3) * 4;
            float4 v = make_float4(0.f, 0.f, 0.f, 0.f);
            int tok = sTok[row];
            if (tok >= 0)
                v = *(const float4*)(x + (size_t)tok * Hn + k0 + c4);
            *(float4*)&sA[row][c4] = v;
        }
        // load Wg / Wu tiles
        {
            int kr = tid >> 4;
            int nc = (tid & 15) * 4;
            size_t off = (size_t)(k0 + kr) * In + n0 + nc;
            *(float4*)&sG[kr][nc] = *(const float4*)(Wg_e + off);
            *(float4*)&sU[kr][nc] = *(const float4*)(Wu_e + off);
        }
        __syncthreads();

        #pragma unroll
        for (int kk = 0; kk < BK; kk++) {
            float a[8];
            #pragma unroll
            for (int i = 0; i < 8; i++) a[i] = sA[ty * 8 + i][kk];
            float4 bg = *(float4*)&sG[kk][tx * 4];
            float4 bu = *(float4*)&sU[kk][tx * 4];
            float bgv[4] = {bg.x, bg.y, bg.z, bg.w};
            float buv[4] = {bu.x, bu.y, bu.z, bu.w};
            #pragma unroll
            for (int i = 0; i < 8; i++) {
                #pragma unroll
                for (int j = 0; j < 4; j++) {
                    accG[i][j] += a[i] * bgv[j];
                    accU[i][j] += a[i] * buv[j];
                }
            }
        }
        __syncthreads();
    }

    // epilogue: silu(g) * u -> g_inter
    #pragma unroll
    for (int i = 0; i < 8; i++) {
        int m = mBase + ty * 8 + i;
        if (m < n_rows) {
            float4 v;
            float* vv = &v.x;
            #pragma unroll
            for (int j = 0; j < 4; j++) {
                float g = accG[i][j];
                float sg = g / (1.0f + __expf(-g));
                vv[j] = sg * accU[i][j];
            }
            *(float4*)(g_inter + ((size_t)e * Tn + m) * In + n0 + tx * 4) = v;
        }
    }
}

// -------- GEMM2: inter @ Wd, weighted scatter into output --------
__global__ __launch_bounds__(256, 2)
void gemm2_kernel(const float* __restrict__ Wd, float* __restrict__ out) {
    int e = blockIdx.z;
    int n_rows = g_cnt[e];
    int mBase = blockIdx.y * BM;
    if (mBase >= n_rows) return;
    int n0 = blockIdx.x * BN;

    __shared__ float sA[BM][BK + 4];
    __shared__ float sB[BK][BN];

    int tid = threadIdx.x;
    int tx = tid & 15;
    int ty = tid >> 4;

    float acc[8][4] = {{0}};
    const float* A = g_inter + (size_t)e * Tn * In;
    const float* B = Wd + (size_t)e * In * Hn;

    for (int k0 = 0; k0 < In; k0 += BK) {
        #pragma unroll
        for (int j = 0; j < 2; j++) {
            int idx = tid + j * 256;
            int row = idx >> 2;
            int c4  = (idx & 3) * 4;
            int m = mBase + row;
            float4 v = make_float4(0.f, 0.f, 0.f, 0.f);
            if (m < n_rows)
                v = *(const float4*)(A + (size_t)m * In + k0 + c4);
            *(float4*)&sA[row][c4] = v;
        }
        {
            int kr = tid >> 4;
            int nc = (tid & 15) * 4;
            *(float4*)&sB[kr][nc] =
                *(const float4*)(B + (size_t)(k0 + kr) * Hn + n0 + nc);
        }
        __syncthreads();

        #pragma unroll
        for (int kk = 0; kk < BK; kk++) {
            float a[8];
            #pragma unroll
            for (int i = 0; i < 8; i++) a[i] = sA[ty * 8 + i][kk];
            float4 b = *(float4*)&sB[kk][tx * 4];
            float bv[4] = {b.x, b.y, b.z, b.w};
            #pragma unroll
            for (int i = 0; i < 8; i++)
                #pragma unroll
                for (int j = 0; j < 4; j++)
                    acc[i][j] += a[i] * bv[j];
        }
        __syncthreads();
    }

    #pragma unroll
    for (int i = 0; i < 8; i++) {
        int m = mBase + ty * 8 + i;
        if (m < n_rows) {
            int tok = g_tok[e * Tn + m];
            float w = g_wt[e * Tn + m];
            float* dst = out + (size_t)tok * Hn + n0 + tx * 4;
            #pragma unroll
            for (int j = 0; j < 4; j++)
                atomicAdd(dst + j, w * acc[i][j]);
        }
    }
}

// -------- launch --------
extern "C" void kernel_launch(void* const* d_in, const int* in_sizes, int n_in,
                              void* d_out, int out_size) {
    const float* x  = (const float*)d_in[0];  // [T, H]
    const float* Wr = (const float*)d_in[1];  // [H, E]
    const float* Wg = (const float*)d_in[2];  // [E, H, I]
    const float* Wu = (const float*)d_in[3];  // [E, H, I]
    const float* Wd = (const float*)d_in[4];  // [E, I, H]
    float* out = (float*)d_out;

    init_kernel<<<(out_size + 255) / 256, 256>>>(out, out_size);
    router_kernel<<<Tn, 256>>>(x, Wr);
    if (out_size > Tn * Hn)
        aux_kernel<<<1, 32>>>(out, Tn * Hn);

    dim3 g1(In / BN, Tn / BM, En);
    gemm1_kernel<<<g1, 256>>>(x, Wg, Wu);

    dim3 g2(Hn / BN, Tn / BM, En);
    gemm2_kernel<<<g2, 256>>>(Wd, out);
}

// round 3
// speedup vs baseline: 2.3186x; 2.3186x over previous
#include <cuda_runtime.h>
#include <cuda_bf16.h>
#include <stdint.h>
#include <math.h>

#define Tn 4096
#define Hn 1024
#define En 8
#define In 1024

// ==================== scratch ====================
__device__ int   g_cnt[En];
__device__ float g_imp[En];
__device__ int   g_tok[En * Tn];
__device__ int   g_tk [Tn * 2];
__device__ float g_tkw[Tn * 2];
__device__ float g_inter[(size_t)En * Tn * In];   // silu(g)*u, fp32
__device__ float g_out2 [(size_t)En * Tn * Hn];   // per-(expert,pos) output

// ==================== helpers ====================
__device__ __forceinline__ uint32_t smem_u32(const void* p) {
    uint32_t a;
    asm("{ .reg .u64 t; cvta.to.shared.u64 t, %1; cvt.u32.u64 %0, t; }" : "=r"(a) : "l"(p));
    return a;
}

#define LDM4(r, addr)                                                          \
    asm volatile("ldmatrix.sync.aligned.m8n8.x4.shared.b16 {%0,%1,%2,%3}, [%4];" \
        : "=r"((r)[0]), "=r"((r)[1]), "=r"((r)[2]), "=r"((r)[3]) : "r"(addr))

#define MMA(d, a, b0, b1)                                                      \
    asm volatile("mma.sync.aligned.m16n8k16.row.col.f32.bf16.bf16.f32 "        \
        "{%0,%1,%2,%3}, {%4,%5,%6,%7}, {%8,%9}, {%0,%1,%2,%3};"                \
        : "+f"((d)[0]), "+f"((d)[1]), "+f"((d)[2]), "+f"((d)[3])               \
        : "r"((a)[0]), "r"((a)[1]), "r"((a)[2]), "r"((a)[3]), "r"(b0), "r"(b1))

// split fp32 pair -> bf16x2 hi + bf16x2 lo (packed u32, low half = first elem)
__device__ __forceinline__ void split2(float a, float b, uint32_t& hi, uint32_t& lo) {
    __nv_bfloat16 ha = __float2bfloat16(a), hb = __float2bfloat16(b);
    float ra = a - __bfloat162float(ha);
    float rb = b - __bfloat162float(hb);
    __nv_bfloat162 H; H.x = ha; H.y = hb;
    __nv_bfloat162 L = __floats2bfloat162_rn(ra, rb);
    hi = *(uint32_t*)&H;  lo = *(uint32_t*)&L;
}

// ==================== small kernels ====================
__global__ void init_kernel() {
    if (threadIdx.x < En) { g_cnt[threadIdx.x] = 0; g_imp[threadIdx.x] = 0.0f; }
}

__global__ void router_kernel(const float* __restrict__ x, const float* __restrict__ Wr) {
    int t = blockIdx.x;
    int warp = threadIdx.x >> 5, lane = threadIdx.x & 31;
    const float* xt = x + (size_t)t * Hn;
    float acc = 0.0f;
    for (int h = lane; h < Hn; h += 32) acc += xt[h] * Wr[h * En + warp];
    #pragma unroll
    for (int o = 16; o > 0; o >>= 1) acc += __shfl_xor_sync(0xffffffff, acc, o);
    __shared__ float logits[En];
    if (lane == 0) logits[warp] = acc;
    __syncthreads();
    if (threadIdx.x == 0) {
        float mx = logits[0];
        #pragma unroll
        for (int e = 1; e < En; e++) mx = fmaxf(mx, logits[e]);
        float p[En], s = 0.0f;
        #pragma unroll
        for (int e = 0; e < En; e++) { p[e] = expf(logits[e] - mx); s += p[e]; }
        float inv = 1.0f / s;
        #pragma unroll
        for (int e = 0; e < En; e++) { p[e] *= inv; atomicAdd(&g_imp[e], p[e]); }
        int i0 = 0;
        #pragma unroll
        for (int e = 1; e < En; e++) if (p[e] > p[i0]) i0 = e;
        int i1 = (i0 == 0) ? 1 : 0;
        #pragma unroll
        for (int e = 0; e < En; e++) if (e != i0 && p[e] > p[i1]) i1 = e;
        float w0 = p[i0], w1 = p[i1];
        float sw = fmaxf(w0 + w1, 1e-9f);
        w0 /= sw; w1 /= sw;
        int p0 = atomicAdd(&g_cnt[i0], 1);
        int p1 = atomicAdd(&g_cnt[i1], 1);
        g_tok[i0 * Tn + p0] = t;
        g_tok[i1 * Tn + p1] = t;
        g_tk [t * 2]     = i0 * Tn + p0;  g_tkw[t * 2]     = w0;
        g_tk [t * 2 + 1] = i1 * Tn + p1;  g_tkw[t * 2 + 1] = w1;
    }
}

__global__ void aux_kernel(float* out, int aux_idx) {
    if (threadIdx.x == 0) {
        float s = 0.0f;
        #pragma unroll
        for (int e = 0; e < En; e++)
            s += ((float)g_cnt[e] / (float)Tn) * (g_imp[e] / (float)Tn);
        out[aux_idx] = (float)En * s * 0.01f;
    }
}

__global__ void combine_kernel(float* __restrict__ out) {
    int t = blockIdx.x;
    int s0 = g_tk[2 * t], s1 = g_tk[2 * t + 1];
    float w0 = g_tkw[2 * t], w1 = g_tkw[2 * t + 1];
    const float4* a = (const float4*)(g_out2 + (size_t)s0 * Hn);
    const float4* b = (const float4*)(g_out2 + (size_t)s1 * Hn);
    float4* o = (float4*)(out + (size_t)t * Hn);
    int i = threadIdx.x;   // 256 threads == Hn/4
    float4 va = a[i], vb = b[i];
    o[i] = make_float4(w0 * va.x + w1 * vb.x, w0 * va.y + w1 * vb.y,
                       w0 * va.z + w1 * vb.z, w0 * va.w + w1 * vb.w);
}

// ==================== smem layout constants ====================
// rows padded to 80 bytes (32 bf16 data + 8 pad) for conflict-free ldmatrix
#define ROWB 80
#define A_BYTES (128 * ROWB)     // 10240
#define B_BYTES (64 * ROWB)      // 5120

// gemm1 stage: Ah, Al, Gh, Gl, Uh, Ul
#define G1_STG (2 * A_BYTES + 4 * B_BYTES)       // 40960
#define G1_SMEM (2 * G1_STG + 512)               // + sTok
// gemm2 stage: Ah, Al, Bh, Bl
#define G2_STG (2 * A_BYTES + 2 * B_BYTES)       // 30720
#define G2_SMEM (2 * G2_STG)

// ==================== GEMM1: X @ {Wg,Wu} -> silu(g)*u -> g_inter ====================
__global__ __launch_bounds__(256, 1)
void gemm1_kernel(const float* __restrict__ x,
                  const float* __restrict__ Wg,
                  const float* __restrict__ Wu) {
    extern __shared__ char smem[];
    int e = blockIdx.z;
    int n_rows = g_cnt[e];
    int mBase = blockIdx.y * 128;
    if (mBase >= n_rows) return;
    int n0 = blockIdx.x * 64;

    uint32_t sb = smem_u32(smem);
    int tid = threadIdx.x, wid = tid >> 5, lane = tid & 31;
    int* sTok = (int*)(smem + 2 * G1_STG);

    if (tid < 128) {
        int m = mBase + tid;
        sTok[tid] = (m < n_rows) ? g_tok[e * Tn + m] : -1;
    }
    __syncthreads();

    const float* Wg_e = Wg + (size_t)e * Hn * In + n0;
    const float* Wu_e = Wu + (size_t)e * Hn * In + n0;

    int an   = tid & 7;         // A: float4 col within row (this thread)
    int bn   = tid & 63;        // B: n within tile
    int bkq  = tid >> 6;        // B: k-quarter (0..3)

    float4 rA[4];
    float rG[8], rU[8];

    // ---- prologue: load + fill stage 0 ----
    #pragma unroll
    for (int it = 0; it < 4; it++) {
        int idx = it * 256 + tid, row = idx >> 3, c4 = idx & 7;
        int tok = sTok[row];
        rA[it] = (tok >= 0) ? *(const float4*)(x + (size_t)tok * Hn + c4 * 4)
                            : make_float4(0.f, 0.f, 0.f, 0.f);
    }
    #pragma unroll
    for (int j = 0; j < 8; j++) {
        size_t o = (size_t)(bkq * 8 + j) * In + bn;
        rG[j] = Wg_e[o];  rU[j] = Wu_e[o];
    }

    float aG[2][4][4] = {{{0}}}, aU[2][4][4] = {{{0}}};

    int wm = wid & 3, wn = wid >> 2;
    int ar = lane & 15, ac = lane >> 4;                 // A ldmatrix addressing
    int brow = (lane >> 4) * 8 + (lane & 7);            // B ldmatrix addressing
    int bhalf = (lane & 15) >> 3;

    #pragma unroll 1
    for (int s = 0; s < 32; s++) {
        int cur = s & 1;
        char* st = smem + cur * G1_STG;

        // store prefetched regs into current buffer
        {
            char* Ah = st;  char* Al = st + A_BYTES;
            #pragma unroll
            for (int it = 0; it < 4; it++) {
                int idx = it * 256 + tid, row = idx >> 3, c4 = idx & 7;
                uint32_t h0, l0, h1, l1;
                split2(rA[it].x, rA[it].y, h0, l0);
                split2(rA[it].z, rA[it].w, h1, l1);
                uint32_t off = row * ROWB + c4 * 8;
                *(uint2*)(Ah + off) = make_uint2(h0, h1);
                *(uint2*)(Al + off) = make_uint2(l0, l1);
            }
            char* Gh = st + 2 * A_BYTES;
            uint32_t gh[4], gl[4], uh[4], ul[4];
            #pragma unroll
            for (int j = 0; j < 4; j++) {
                split2(rG[2 * j], rG[2 * j + 1], gh[j], gl[j]);
                split2(rU[2 * j], rU[2 * j + 1], uh[j], ul[j]);
            }
            uint32_t boff = bn * ROWB + bkq * 16;
            *(uint4*)(Gh + boff)               = make_uint4(gh[0], gh[1], gh[2], gh[3]);
            *(uint4*)(Gh + B_BYTES + boff)     = make_uint4(gl[0], gl[1], gl[2], gl[3]);
            *(uint4*)(Gh + 2 * B_BYTES + boff) = make_uint4(uh[0], uh[1], uh[2], uh[3]);
            *(uint4*)(Gh + 3 * B_BYTES + boff) = make_uint4(ul[0], ul[1], ul[2], ul[3]);
        }
        __syncthreads();

        // issue LDGs for next stage
        if (s < 31) {
            int k0 = (s + 1) * 32;
            #pragma unroll
            for (int it = 0; it < 4; it++) {
                int idx = it * 256 + tid, row = idx >> 3, c4 = idx & 7;
                int tok = sTok[row];
                rA[it] = (tok >= 0) ? *(const float4*)(x + (size_t)tok * Hn + k0 + c4 * 4)
                                    : make_float4(0.f, 0.f, 0.f, 0.f);
            }
            #pragma unroll
            for (int j = 0; j < 8; j++) {
                size_t o = (size_t)(k0 + bkq * 8 + j) * In + bn;
                rG[j] = Wg_e[o];  rU[j] = Wu_e[o];
            }
        }

        // compute current stage
        uint32_t aBase = sb + cur * G1_STG;
        uint32_t gBase = aBase + 2 * A_BYTES;
        #pragma unroll
        for (int kk = 0; kk < 2; kk++) {
            int kb = kk * 32;
            uint32_t ah[2][4], al[2][4];
            #pragma unroll
            for (int mt = 0; mt < 2; mt++) {
                uint32_t ad = aBase + (uint32_t)(wm * 32 + mt * 16 + ar) * ROWB + kb + ac * 16;
                LDM4(ah[mt], ad);
                LDM4(al[mt], ad + A_BYTES);
            }
            uint32_t bgh[2][4], bgl[2][4], buh[2][4], bul[2][4];
            #pragma unroll
            for (int ng = 0; ng < 2; ng++) {
                uint32_t bd = gBase + (uint32_t)(wn * 32 + ng * 16 + brow) * ROWB + kb + bhalf * 16;
                LDM4(bgh[ng], bd);
                LDM4(bgl[ng], bd + B_BYTES);
                LDM4(buh[ng], bd + 2 * B_BYTES);
                LDM4(bul[ng], bd + 3 * B_BYTES);
            }
            // pass 1: hi*hi
            #pragma unroll
            for (int mt = 0; mt < 2; mt++)
                #pragma unroll
                for (int nt = 0; nt < 4; nt++) {
                    int ng = nt >> 1, p = (nt & 1) * 2;
                    MMA(aG[mt][nt], ah[mt], bgh[ng][p], bgh[ng][p + 1]);
                    MMA(aU[mt][nt], ah[mt], buh[ng][p], buh[ng][p + 1]);
                }
            // pass 2: hi*lo
            #pragma unroll
            for (int mt = 0; mt < 2; mt++)
                #pragma unroll
                for (int nt = 0; nt < 4; nt++) {
                    int ng = nt >> 1, p = (nt & 1) * 2;
                    MMA(aG[mt][nt], ah[mt], bgl[ng][p], bgl[ng][p + 1]);
                    MMA(aU[mt][nt], ah[mt], bul[ng][p], bul[ng][p + 1]);
                }
            // pass 3: lo*hi
            #pragma unroll
            for (int mt = 0; mt < 2; mt++)
                #pragma unroll
                for (int nt = 0; nt < 4; nt++) {
                    int ng = nt >> 1, p = (nt & 1) * 2;
                    MMA(aG[mt][nt], al[mt], bgh[ng][p], bgh[ng][p + 1]);
                    MMA(aU[mt][nt], al[mt], buh[ng][p], buh[ng][p + 1]);
                }
        }
        __syncthreads();
    }

    // epilogue: silu(g)*u -> g_inter (fp32)
    #pragma unroll
    for (int mt = 0; mt < 2; mt++) {
        #pragma unroll
        for (int nt = 0; nt < 4; nt++) {
            int c = n0 + wn * 32 + nt * 8 + (lane & 3) * 2;
            #pragma unroll
            for (int h = 0; h < 2; h++) {
                int r = mBase + wm * 32 + mt * 16 + (lane >> 2) + h * 8;
                if (r < n_rows) {
                    float g0 = aG[mt][nt][h * 2],     u0 = aU[mt][nt][h * 2];
                    float g1 = aG[mt][nt][h * 2 + 1], u1 = aU[mt][nt][h * 2 + 1];
                    float i0 = u0 * g0 / (1.0f + __expf(-g0));
                    float i1 = u1 * g1 / (1.0f + __expf(-g1));
                    *(float2*)(g_inter + ((size_t)e * Tn + r) * In + c) = make_float2(i0, i1);
                }
            }
        }
    }
}

// ==================== GEMM2: inter @ Wd -> g_out2 ====================
__global__ __launch_bounds__(256, 1)
void gemm2_kernel(const float* __restrict__ Wd) {
    extern __shared__ char smem[];
    int e = blockIdx.z;
    int n_rows = g_cnt[e];
    int mBase = blockIdx.y * 128;
    if (mBase >= n_rows) return;
    int n0 = blockIdx.x * 64;

    uint32_t sb = smem_u32(smem);
    int tid = threadIdx.x, wid = tid >> 5, lane = tid & 31;

    const float* A  = g_inter + (size_t)e * Tn * In;
    const float* Bw = Wd + (size_t)e * In * Hn + n0;

    int bn  = tid & 63;
    int bkq = tid >> 6;

    float4 rA[4];
    float rB[8];

    #pragma unroll
    for (int it = 0; it < 4; it++) {
        int idx = it * 256 + tid, row = idx >> 3, c4 = idx & 7;
        int m = mBase + row;
        rA[it] = (m < n_rows) ? *(const float4*)(A + (size_t)m * In + c4 * 4)
                              : make_float4(0.f, 0.f, 0.f, 0.f);
    }
    #pragma unroll
    for (int j = 0; j < 8; j++)
        rB[j] = Bw[(size_t)(bkq * 8 + j) * Hn + bn];

    float acc[2][4][4] = {{{0}}};

    int wm = wid & 3, wn = wid >> 2;
    int ar = lane & 15, ac = lane >> 4;
    int brow = (lane >> 4) * 8 + (lane & 7);
    int bhalf = (lane & 15) >> 3;

    #pragma unroll 1
    for (int s = 0; s < 32; s++) {
        int cur = s & 1;
        char* st = smem + cur * G2_STG;
        {
            char* Ah = st;  char* Al = st + A_BYTES;
            #pragma unroll
            for (int it = 0; it < 4; it++) {
                int idx = it * 256 + tid, row = idx >> 3, c4 = idx & 7;
                uint32_t h0, l0, h1, l1;
                split2(rA[it].x, rA[it].y, h0, l0);
                split2(rA[it].z, rA[it].w, h1, l1);
                uint32_t off = row * ROWB + c4 * 8;
                *(uint2*)(Ah + off) = make_uint2(h0, h1);
                *(uint2*)(Al + off) = make_uint2(l0, l1);
            }
            char* Bh = st + 2 * A_BYTES;
            uint32_t bh[4], bl[4];
            #pragma unroll
            for (int j = 0; j < 4; j++)
                split2(rB[2 * j], rB[2 * j + 1], bh[j], bl[j]);
            uint32_t boff = bn * ROWB + bkq * 16;
            *(uint4*)(Bh + boff)           = make_uint4(bh[0], bh[1], bh[2], bh[3]);
            *(uint4*)(Bh + B_BYTES + boff) = make_uint4(bl[0], bl[1], bl[2], bl[3]);
        }
        __syncthreads();

        if (s < 31) {
            int k0 = (s + 1) * 32;
            #pragma unroll
            for (int it = 0; it < 4; it++) {
                int idx = it * 256 + tid, row = idx >> 3, c4 = idx & 7;
                int m = mBase + row;
                rA[it] = (m < n_rows) ? *(const float4*)(A + (size_t)m * In + k0 + c4 * 4)
                                      : make_float4(0.f, 0.f, 0.f, 0.f);
            }
            #pragma unroll
            for (int j = 0; j < 8; j++)
                rB[j] = Bw[(size_t)(k0 + bkq * 8 + j) * Hn + bn];
        }

        uint32_t aBase = sb + cur * G2_STG;
        uint32_t bBase = aBase + 2 * A_BYTES;
        #pragma unroll
        for (int kk = 0; kk < 2; kk++) {
            int kb = kk * 32;
            uint32_t ah[2][4], al[2][4];
            #pragma unroll
            for (int mt = 0; mt < 2; mt++) {
                uint32_t ad = aBase + (uint32_t)(wm * 32 + mt * 16 + ar) * ROWB + kb + ac * 16;
                LDM4(ah[mt], ad);
                LDM4(al[mt], ad + A_BYTES);
            }
            uint32_t bh[2][4], bl[2][4];
            #pragma unroll
            for (int ng = 0; ng < 2; ng++) {
                uint32_t bd = bBase + (uint32_t)(wn * 32 + ng * 16 + brow) * ROWB + kb + bhalf * 16;
                LDM4(bh[ng], bd);
                LDM4(bl[ng], bd + B_BYTES);
            }
            #pragma unroll
            for (int mt = 0; mt < 2; mt++)
                #pragma unroll
                for (int nt = 0; nt < 4; nt++) {
                    int ng = nt >> 1, p = (nt & 1) * 2;
                    MMA(acc[mt][nt], ah[mt], bh[ng][p], bh[ng][p + 1]);
                }
            #pragma unroll
            for (int mt = 0; mt < 2; mt++)
                #pragma unroll
                for (int nt = 0; nt < 4; nt++) {
                    int ng = nt >> 1, p = (nt & 1) * 2;
                    MMA(acc[mt][nt], ah[mt], bl[ng][p], bl[ng][p + 1]);
                }
            #pragma unroll
            for (int mt = 0; mt < 2; mt++)
                #pragma unroll
                for (int nt = 0; nt < 4; nt++) {
                    int ng = nt >> 1, p = (nt & 1) * 2;
                    MMA(acc[mt][nt], al[mt], bh[ng][p], bh[ng][p + 1]);
                }
        }
        __syncthreads();
    }

    #pragma unroll
    for (int mt = 0; mt < 2; mt++) {
        #pragma unroll
        for (int nt = 0; nt < 4; nt++) {
            int c = n0 + wn * 32 + nt * 8 + (lane & 3) * 2;
            #pragma unroll
            for (int h = 0; h < 2; h++) {
                int r = mBase + wm * 32 + mt * 16 + (lane >> 2) + h * 8;
                if (r < n_rows) {
                    *(float2*)(g_out2 + ((size_t)e * Tn + r) * Hn + c) =
                        make_float2(acc[mt][nt][h * 2], acc[mt][nt][h * 2 + 1]);
                }
            }
        }
    }
}

// ==================== launch ====================
extern "C" void kernel_launch(void* const* d_in, const int* in_sizes, int n_in,
                              void* d_out, int out_size) {
    const float* x  = (const float*)d_in[0];
    const float* Wr = (const float*)d_in[1];
    const float* Wg = (const float*)d_in[2];
    const float* Wu = (const float*)d_in[3];
    const float* Wd = (const float*)d_in[4];
    float* out = (float*)d_out;

    cudaFuncSetAttribute(gemm1_kernel, cudaFuncAttributeMaxDynamicSharedMemorySize, G1_SMEM);
    cudaFuncSetAttribute(gemm2_kernel, cudaFuncAttributeMaxDynamicSharedMemorySize, G2_SMEM);

    init_kernel<<<1, 32>>>();
    router_kernel<<<Tn, 256>>>(x, Wr);
    if (out_size > Tn * Hn)
        aux_kernel<<<1, 32>>>(out, Tn * Hn);

    dim3 g1(In / 64, Tn / 128, En);
    gemm1_kernel<<<g1, 256, G1_SMEM>>>(x, Wg, Wu);

    dim3 g2(Hn / 64, Tn / 128, En);
    gemm2_kernel<<<g2, 256, G2_SMEM>>>(Wd);

    combine_kernel<<<Tn, 256>>>(out);
}